// round 16
// baseline (speedup 1.0000x reference)
#include <cuda_runtime.h>
#include <cuda_bf16.h>
#include <math.h>

#define SCALE1 0.17677669529663687f  // 32^-0.5
typedef __nv_bfloat16 bf16;

// ---------------- scratch (static device globals; no allocation) ------------
__device__ float g_proj1[16384*768];   // [q1 | q2 | kv2(k,v) | lepe_lin]
__device__ float g_xs_pre[4096*256];
__device__ float g_cat[16384*256];     // [x1 | x2]
__device__ float g_part[4*512*1024];
__device__ float g_gsum[4*1024];
__device__ float g_lm[4*4096];
__device__ float g_bcat[768];
__device__ float g_lwT[9*256];         // (tap, c)
// bf16 hi/lo-split operands: A'' = [hi|lo|hi], B'' = [hi|hi|lo]
__device__ bf16  g_xhl[16384*768];     // x split
__device__ bf16  g_prehl[16384*768];   // (cat+lepe) split
__device__ bf16  g_xshl[4096*768];     // gelu(ln(xs)) split
__device__ bf16  g_WcatB[768*768];     // [n][k'']
__device__ bf16  g_srwB[256*3072];     // [n][k''] for SR conv
__device__ bf16  g_pwB[256*768];
__device__ bf16  g_kv1B[256*768];
// attention bf16-split tensors
__device__ bf16  g_q1hl[16*4096*96];   // [(b,h)][tok][ {hi|lo|hi} d32 ]
__device__ bf16  g_k1hl[16*1024*96];   // [(b,h)][key][ {hi|hi|lo} d32 ]
__device__ bf16  g_v1T [16*32*3072];   // [(b,h)][dd][ chunk*384 + {hi|hi|lo} key128 ]

// ---------------- helpers ---------------------------------------------------
__device__ __forceinline__ float wredmax(float v){
  #pragma unroll
  for(int o=16;o;o>>=1) v = fmaxf(v, __shfl_xor_sync(0xFFFFFFFFu, v, o));
  return v;
}
__device__ __forceinline__ float wredsum(float v){
  #pragma unroll
  for(int o=16;o;o>>=1) v += __shfl_xor_sync(0xFFFFFFFFu, v, o);
  return v;
}
__device__ __forceinline__ void mma_bf16(float4& c, const unsigned a[4], unsigned b0, unsigned b1){
  asm("mma.sync.aligned.m16n8k16.row.col.f32.bf16.bf16.f32 "
      "{%0,%1,%2,%3}, {%4,%5,%6,%7}, {%8,%9}, {%0,%1,%2,%3};"
      : "+f"(c.x), "+f"(c.y), "+f"(c.z), "+f"(c.w)
      : "r"(a[0]), "r"(a[1]), "r"(a[2]), "r"(a[3]), "r"(b0), "r"(b1));
}
__device__ __forceinline__ void split2(float v, bf16& hi, bf16& lo){
  hi = __float2bfloat16(v);
  lo = __float2bfloat16(v - __bfloat162float(hi));
}
__device__ __forceinline__ unsigned sm_u32(const void* p){
  return (unsigned)__cvta_generic_to_shared(p);
}
__device__ __forceinline__ void ldsm_x4(unsigned r[4], unsigned addr){
  asm volatile("ldmatrix.sync.aligned.m8n8.x4.shared.b16 {%0,%1,%2,%3}, [%4];"
    : "=r"(r[0]),"=r"(r[1]),"=r"(r[2]),"=r"(r[3]) : "r"(addr));
}
__device__ __forceinline__ void cpa16(unsigned saddr, const void* g){
  asm volatile("cp.async.cg.shared.global [%0], [%1], 16;" :: "r"(saddr), "l"(g));
}

__global__ void nop_k(){}

// ---------------- weight prep ------------------------------------------------
__global__ void prep_k(const float* __restrict__ q1w, const float* __restrict__ q2w,
                       const float* __restrict__ kv2w, const float* __restrict__ lpw,
                       const float* __restrict__ q1b, const float* __restrict__ q2b,
                       const float* __restrict__ kv2b, const float* __restrict__ lpb,
                       const float* __restrict__ srw, const float* __restrict__ lcw,
                       const float* __restrict__ kv1w, const float* __restrict__ pw)
{
  int i0 = blockIdx.x*blockDim.x + threadIdx.x;
  int st = gridDim.x*blockDim.x;
  for(int c=i0;c<768;c+=st)
    g_bcat[c] = (c<128)?q1b[c]:(c<256)?q2b[c-128]:(c<512)?kv2b[c-256]:lpb[c-512];
  for(int idx=i0; idx<9*256; idx+=st){
    int tap = idx>>8, c = idx&255;
    g_lwT[idx] = lcw[c*9+tap];
  }
  for(int idx=i0; idx<768*256; idx+=st){
    int n = idx>>8, k = idx&255;
    float w = (n<128)? q1w[k*128+n] : (n<256)? q2w[k*128+(n-128)]
            : (n<512)? kv2w[k*256+(n-256)] : lpw[k*256+(n-512)];
    bf16 hi, lo; split2(w, hi, lo);
    g_WcatB[n*768 + k]       = hi;
    g_WcatB[n*768 + 256 + k] = hi;
    g_WcatB[n*768 + 512 + k] = lo;
  }
  for(int idx=i0; idx<256*1024; idx+=st){
    int n = idx>>10, k = idx&1023;
    float w = srw[(n*256 + (k&255))*4 + (k>>8)];
    bf16 hi, lo; split2(w, hi, lo);
    g_srwB[n*3072 + k]        = hi;
    g_srwB[n*3072 + 1024 + k] = hi;
    g_srwB[n*3072 + 2048 + k] = lo;
  }
  for(int idx=i0; idx<256*256; idx+=st){
    int n = idx>>8, k = idx&255;
    bf16 hi, lo;
    split2(pw[k*256+n], hi, lo);
    g_pwB[n*768+k] = hi; g_pwB[n*768+256+k] = hi; g_pwB[n*768+512+k] = lo;
    split2(kv1w[k*256+n], hi, lo);
    g_kv1B[n*768+k] = hi; g_kv1B[n*768+256+k] = hi; g_kv1B[n*768+512+k] = lo;
  }
}

// ---------------- x -> hi/lo split -------------------------------------------
__global__ void convx_k(const float* __restrict__ x){
  int m = blockIdx.x, c = threadIdx.x;
  float v = x[(size_t)m*256+c];
  bf16 hi, lo; split2(v, hi, lo);
  size_t b = (size_t)m*768;
  g_xhl[b+c] = hi; g_xhl[b+256+c] = lo; g_xhl[b+512+c] = hi;
}

// ---------------- bf16-split MMA GEMM (R13-verified) -------------------------
// MODE 0: g_xhl   @ g_WcatB (K''=768, Nn=768) +g_bcat -> g_proj1 (+ q1hl)
// MODE 1: gather(g_xhl) @ g_srwB (K''=3072, Nn=256) +srb -> g_xs_pre
// MODE 2: g_xshl  @ g_kv1B (768, 256) +kv1b -> g_k1hl / g_v1T (bf16 only)
// MODE 3: g_prehl @ g_pwB  (768, 256) +pb, x2 -> d_out
extern __shared__ float dsm[];
template<int MODE>
__device__ __forceinline__ void gemm_mma(const bf16* __restrict__ Ag,
                                         const bf16* __restrict__ Bg,
                                         const float* __restrict__ bi,
                                         float* __restrict__ C,
                                         int by, int bx)
{
  constexpr int K2 = (MODE==1)?3072:768;
  constexpr int Nn = (MODE==0)?768:256;
  constexpr int NKC = K2/64;
  bf16* sAb = (bf16*)dsm;
  bf16* sBb = sAb + 2*128*72;
  int t = threadIdx.x;
  int m0 = by*128, n0 = bx*128;
  int wid = t>>5, lane = t&31;
  int wm = wid>>1, wn = wid&1;
  int g = lane>>2, tg = lane&3;
  int lane15 = lane&15, lk8 = ((lane>>4)&1)*8;
  float4 acc[2][8];
  #pragma unroll
  for(int i=0;i<2;i++)
    #pragma unroll
    for(int j=0;j<8;j++) acc[i][j] = make_float4(0.f,0.f,0.f,0.f);

  auto issue_tile = [&](int kc, int s){
    bf16* sA = sAb + s*(128*72);
    bf16* sB = sBb + s*(128*72);
    #pragma unroll
    for(int i=0;i<4;i++){
      int e = t + (i<<8);
      int r = e>>3, c8 = e&7;
      const bf16* ap;
      if constexpr (MODE==1){
        int gr = m0 + r;
        int bb = gr>>10, p = gr&1023, ii = p>>5, jj = p&31;
        int sseg = kc>>4;
        int seg  = (kc>>2)&3;
        int ic0  = (kc&3)*64;
        int tok = (bb<<12) + ((2*ii + (seg>>1))<<6) + 2*jj + (seg&1);
        ap = Ag + (size_t)tok*768 + sseg*256 + ic0 + c8*8;
      } else {
        ap = Ag + (size_t)(m0+r)*K2 + kc*64 + c8*8;
      }
      cpa16(sm_u32(&sA[r*72 + c8*8]), ap);
      cpa16(sm_u32(&sB[r*72 + c8*8]), Bg + (size_t)(n0+r)*K2 + kc*64 + c8*8);
    }
    asm volatile("cp.async.commit_group;" ::: "memory");
  };

  issue_tile(0, 0);
  for(int kc=0; kc<NKC; kc++){
    int s = kc&1;
    bf16* sA = sAb + s*(128*72);
    bf16* sB = sBb + s*(128*72);
    asm volatile("cp.async.wait_group 0;" ::: "memory");
    __syncthreads();
    if(kc+1 < NKC) issue_tile(kc+1, s^1);
    #pragma unroll
    for(int ks=0; ks<4; ks++){
      unsigned a[2][4], bq[4][4];
      #pragma unroll
      for(int mt=0;mt<2;mt++)
        ldsm_x4(a[mt], sm_u32(&sA[(wm*32 + mt*16 + lane15)*72 + ks*16 + lk8]));
      #pragma unroll
      for(int p=0;p<4;p++)
        ldsm_x4(bq[p], sm_u32(&sB[(wn*64 + p*16 + lane15)*72 + ks*16 + lk8]));
      #pragma unroll
      for(int mt=0;mt<2;mt++)
        #pragma unroll
        for(int nt=0;nt<8;nt++)
          mma_bf16(acc[mt][nt], a[mt], bq[nt>>1][nt&1], bq[nt>>1][2+(nt&1)]);
    }
    __syncthreads();
  }
  #pragma unroll
  for(int mt=0;mt<2;mt++){
    int r0 = m0 + wm*32 + mt*16 + g;
    #pragma unroll
    for(int nt=0;nt<8;nt++){
      int c0 = n0 + wn*64 + nt*8 + 2*tg;
      float2 v0 = make_float2(acc[mt][nt].x + bi[c0], acc[mt][nt].y + bi[c0+1]);
      float2 v1 = make_float2(acc[mt][nt].z + bi[c0], acc[mt][nt].w + bi[c0+1]);
      if(MODE==3){ v0.x*=2.f; v0.y*=2.f; v1.x*=2.f; v1.y*=2.f; }
      if(MODE!=2){
        *(float2*)&C[(size_t)r0*Nn + c0]     = v0;
        *(float2*)&C[(size_t)(r0+8)*Nn + c0] = v1;
      }
      if(MODE==0 && c0 < 128){
        int hh = c0>>5, dq = c0&31;
        int bb = r0>>12, nn = r0&4095;
        size_t b0 = ((size_t)(bb*4+hh)*4096 + nn)*96;
        size_t b1 = b0 + 8*96;
        bf16 hi,lo;
        split2(v0.x,hi,lo); g_q1hl[b0+dq]=hi;   g_q1hl[b0+32+dq]=lo;   g_q1hl[b0+64+dq]=hi;
        split2(v0.y,hi,lo); g_q1hl[b0+dq+1]=hi; g_q1hl[b0+32+dq+1]=lo; g_q1hl[b0+64+dq+1]=hi;
        split2(v1.x,hi,lo); g_q1hl[b1+dq]=hi;   g_q1hl[b1+32+dq]=lo;   g_q1hl[b1+64+dq]=hi;
        split2(v1.y,hi,lo); g_q1hl[b1+dq+1]=hi; g_q1hl[b1+32+dq+1]=lo; g_q1hl[b1+64+dq+1]=hi;
      }
      if(MODE==2){
        int bb = r0>>10, key = r0&1023;
        bf16 hi,lo;
        if(c0 < 128){
          int hh = c0>>5, dk = c0&31;
          size_t b0 = ((size_t)(bb*4+hh)*1024 + key)*96;
          size_t b1 = b0 + 8*96;
          split2(v0.x,hi,lo); g_k1hl[b0+dk]=hi;   g_k1hl[b0+32+dk]=hi;   g_k1hl[b0+64+dk]=lo;
          split2(v0.y,hi,lo); g_k1hl[b0+dk+1]=hi; g_k1hl[b0+32+dk+1]=hi; g_k1hl[b0+64+dk+1]=lo;
          split2(v1.x,hi,lo); g_k1hl[b1+dk]=hi;   g_k1hl[b1+32+dk]=hi;   g_k1hl[b1+64+dk]=lo;
          split2(v1.y,hi,lo); g_k1hl[b1+dk+1]=hi; g_k1hl[b1+32+dk+1]=hi; g_k1hl[b1+64+dk+1]=lo;
        } else {
          int hh = (c0-128)>>5, dd = (c0-128)&31;
          int cv = key>>7, kk = key&127;
          int cv2 = (key+8)>>7, kk2 = (key+8)&127;
          size_t ba  = ((size_t)(bb*4+hh)*32+dd)*3072 + cv*384;
          size_t bab = ba + 3072;                 // col dd+1
          size_t ba2 = ((size_t)(bb*4+hh)*32+dd)*3072 + cv2*384;
          size_t ba2b= ba2 + 3072;
          split2(v0.x,hi,lo); g_v1T[ba+kk]=hi;    g_v1T[ba+128+kk]=hi;    g_v1T[ba+256+kk]=lo;
          split2(v0.y,hi,lo); g_v1T[bab+kk]=hi;   g_v1T[bab+128+kk]=hi;   g_v1T[bab+256+kk]=lo;
          split2(v1.x,hi,lo); g_v1T[ba2+kk2]=hi;  g_v1T[ba2+128+kk2]=hi;  g_v1T[ba2+256+kk2]=lo;
          split2(v1.y,hi,lo); g_v1T[ba2b+kk2]=hi; g_v1T[ba2b+128+kk2]=hi; g_v1T[ba2b+256+kk2]=lo;
        }
      }
    }
  }
}

#define GEMM_SMEM (4*128*72*2)  // 73728 B

__global__ void __launch_bounds__(256,2) gemm01_k(const float* __restrict__ srb){
  int bid = blockIdx.x;
  if(bid < 768) gemm_mma<0>(g_xhl, g_WcatB, g_bcat, g_proj1, bid/6, bid%6);
  else { int b2 = bid-768; gemm_mma<1>(g_xhl, g_srwB, srb, g_xs_pre, b2>>1, b2&1); }
}
__global__ void __launch_bounds__(256,2) gemm2_k(const float* __restrict__ kv1b){
  gemm_mma<2>(g_xshl, g_kv1B, kv1b, nullptr, blockIdx.x>>1, blockIdx.x&1);
}
__global__ void __launch_bounds__(256,2) gemm3_k(const float* __restrict__ pb, float* __restrict__ out){
  gemm_mma<3>(g_prehl, g_pwB, pb, out, blockIdx.x>>1, blockIdx.x&1);
}

// ---------------- LayerNorm + exact GELU -> hi/lo split ----------------------
__global__ void ln_gelu_k(const float* __restrict__ nw, const float* __restrict__ nb){
  int r = blockIdx.x, c = threadIdx.x;
  float v = g_xs_pre[(size_t)r*256+c];
  float s = v, s2 = v*v;
  #pragma unroll
  for(int o=16;o;o>>=1){ s += __shfl_xor_sync(~0u,s,o); s2 += __shfl_xor_sync(~0u,s2,o); }
  __shared__ float rs[8], rs2[8];
  int w = c>>5, l = c&31;
  if(l==0){ rs[w]=s; rs2[w]=s2; }
  __syncthreads();
  if(w==0){
    float a=(l<8)?rs[l]:0.f, a2=(l<8)?rs2[l]:0.f;
    #pragma unroll
    for(int o=4;o;o>>=1){ a+=__shfl_xor_sync(~0u,a,o); a2+=__shfl_xor_sync(~0u,a2,o); }
    if(l==0){ rs[0]=a; rs2[0]=a2; }
  }
  __syncthreads();
  float m  = rs[0]*(1.f/256.f);
  float var= rs2[0]*(1.f/256.f) - m*m;
  float y  = (v-m)*rsqrtf(var+1e-5f)*nw[c] + nb[c];
  float gv = 0.5f*y*(1.f+erff(y*0.70710678118f));
  bf16 hi, lo; split2(gv, hi, lo);
  size_t b = (size_t)r*768;
  g_xshl[b+c] = hi; g_xshl[b+256+c] = lo; g_xshl[b+512+c] = hi;
}

// ---------------- branch-1 attention: bf16-split mma.sync --------------------
// grid (128 qt, 4 h, 4 b), 256 thr.
// smem: sS fp32 32x1032 (132096B) | sQ/sP bf16 @66048 | 2 KV bufs @78592 (+s*13312)
__global__ void attn1_k(){
  float* sS = dsm;
  bf16* sb  = (bf16*)dsm;
  bf16* sQ  = sb + 66048;     // 32 x 112 (scores phase)
  bf16* sP  = sb + 66048;     // 32 x 392 (AV phase)
  bf16* sKV = sb + 78592;     // 2 x 13312
  int t = threadIdx.x;
  int qt = blockIdx.x, h = blockIdx.y, b = blockIdx.z;
  int n0 = qt*32;
  int wid=t>>5, lane=t&31;
  int wm=wid>>2, wk=wid&3;
  int g=lane>>2, tg=lane&3;
  int lane15=lane&15, lk8=((lane>>4)&1)*8;
  size_t bh = (size_t)(b*4+h);

  auto issueK = [&](int c, int s){
    bf16* kb = sKV + s*13312;
    #pragma unroll
    for(int i=0;i<6;i++){
      int e = t + (i<<8);
      int row = e/12, c8 = e%12;
      cpa16(sm_u32(kb + row*104 + c8*8),
            g_k1hl + (bh*1024 + (size_t)c*128 + row)*96 + c8*8);
    }
    asm volatile("cp.async.commit_group;" ::: "memory");
  };
  auto issueV = [&](int c, int s){
    bf16* vb = sKV + s*13312;
    #pragma unroll
    for(int i=0;i<6;i++){
      int e = t + (i<<8);
      int row = e/48, c8 = e%48;
      cpa16(sm_u32(vb + row*392 + c8*8),
            g_v1T + (bh*32 + row)*3072 + (size_t)c*384 + c8*8);
    }
    asm volatile("cp.async.commit_group;" ::: "memory");
  };

  issueK(0,0); issueK(1,1);
  for(int e=t; e<384; e+=256){
    int row = e/12, c8 = e%12;
    *(uint4*)(sQ + row*112 + c8*8) =
      *(const uint4*)(g_q1hl + (bh*4096 + n0 + row)*96 + c8*8);
  }
  __syncthreads();
  unsigned aq[6][4];
  #pragma unroll
  for(int kt=0;kt<6;kt++)
    ldsm_x4(aq[kt], sm_u32(sQ + (wm*16+lane15)*112 + kt*16 + lk8));

  // ---- scores ----
  for(int c=0;c<8;c++){
    int s = c&1;
    if(c<7) asm volatile("cp.async.wait_group 1;" ::: "memory");
    else    asm volatile("cp.async.wait_group 0;" ::: "memory");
    __syncthreads();
    bf16* kb = sKV + s*13312;
    unsigned bq[2][6][4];
    #pragma unroll
    for(int kg=0;kg<2;kg++)
      #pragma unroll
      for(int kt=0;kt<6;kt++)
        ldsm_x4(bq[kg][kt], sm_u32(kb + (wk*32 + kg*16 + lane15)*104 + kt*16 + lk8));
    float4 acc[4];
    #pragma unroll
    for(int nt=0;nt<4;nt++) acc[nt] = make_float4(0.f,0.f,0.f,0.f);
    #pragma unroll
    for(int kt=0;kt<6;kt++)
      #pragma unroll
      for(int nt=0;nt<4;nt++)
        mma_bf16(acc[nt], aq[kt], bq[nt>>1][kt][nt&1], bq[nt>>1][kt][2+(nt&1)]);
    #pragma unroll
    for(int nt=0;nt<4;nt++){
      int key = (c<<7) + wk*32 + nt*8 + 2*tg;
      int q0 = wm*16+g;
      *(float2*)&sS[q0*1032+key]     = make_float2(acc[nt].x*SCALE1, acc[nt].y*SCALE1);
      *(float2*)&sS[(q0+8)*1032+key] = make_float2(acc[nt].z*SCALE1, acc[nt].w*SCALE1);
    }
    __syncthreads();
    if(c+2<8) issueK(c+2, s);
  }

  issueV(0,0); issueV(1,1);

  // ---- softmax: warp w owns rows w*4..w*4+3 ----
  {
    int w = t>>5, l = t&31;
    for(int qi=0;qi<4;qi++){
      float4* row4 = (float4*)(sS + (w*4+qi)*1032);
      float mx = -1e30f;
      #pragma unroll
      for(int i2=0;i2<8;i2++){
        float4 v = row4[l + 32*i2];
        mx = fmaxf(mx, fmaxf(fmaxf(v.x,v.y), fmaxf(v.z,v.w)));
      }
      mx = wredmax(mx);
      float sm = 0.f;
      #pragma unroll
      for(int i2=0;i2<8;i2++){
        float4 v = row4[l + 32*i2];
        v.x = __expf(v.x-mx); v.y = __expf(v.y-mx);
        v.z = __expf(v.z-mx); v.w = __expf(v.w-mx);
        row4[l+32*i2] = v;
        sm += (v.x+v.y)+(v.z+v.w);
      }
      sm = wredsum(sm);
      float inv = 1.f/sm;
      #pragma unroll
      for(int i2=0;i2<8;i2++){
        float4 v = row4[l+32*i2];
        v.x*=inv; v.y*=inv; v.z*=inv; v.w*=inv;
        row4[l+32*i2] = v;
      }
    }
  }
  __syncthreads();

  // ---- per-key prob sums for g ----
  {
    float4 s4 = make_float4(0.f,0.f,0.f,0.f);
    #pragma unroll 8
    for(int q=0;q<32;q++){
      float4 v = *(const float4*)&sS[q*1032 + t*4];
      s4.x+=v.x; s4.y+=v.y; s4.z+=v.z; s4.w+=v.w;
    }
    *(float4*)&g_part[((size_t)(b*512 + h*128 + qt))*1024 + t*4] = s4;
  }

  // ---- AV: P''(32x384/chunk) x V''T(32x384/chunk) ----
  float4 acc2[4];
  #pragma unroll
  for(int nt=0;nt<4;nt++) acc2[nt] = make_float4(0.f,0.f,0.f,0.f);
  for(int c=0;c<8;c++){
    int s = c&1;
    #pragma unroll
    for(int i=0;i<8;i++){
      int e = t + (i<<8);
      int q = e>>6, k2 = (e&63)<<1;
      float2 p2 = *(float2*)&sS[q*1032 + (c<<7) + k2];
      bf16 h0,l0,h1,l1; split2(p2.x,h0,l0); split2(p2.y,h1,l1);
      __nv_bfloat162 hh; hh.x=h0; hh.y=h1;
      __nv_bfloat162 ll; ll.x=l0; ll.y=l1;
      *(__nv_bfloat162*)(sP + q*392 + k2)       = hh;
      *(__nv_bfloat162*)(sP + q*392 + 128 + k2) = ll;
      *(__nv_bfloat162*)(sP + q*392 + 256 + k2) = hh;
    }
    if(c<7) asm volatile("cp.async.wait_group 1;" ::: "memory");
    else    asm volatile("cp.async.wait_group 0;" ::: "memory");
    __syncthreads();
    bf16* vb = sKV + s*13312;
    unsigned bv[2][6][4];
    #pragma unroll
    for(int kg=0;kg<2;kg++)
      #pragma unroll
      for(int kt=0;kt<6;kt++)
        ldsm_x4(bv[kg][kt], sm_u32(vb + (kg*16+lane15)*392 + wk*96 + kt*16 + lk8));
    #pragma unroll
    for(int kt=0;kt<6;kt++){
      unsigned ap[4];
      ldsm_x4(ap, sm_u32(sP + (wm*16+lane15)*392 + wk*96 + kt*16 + lk8));
      #pragma unroll
      for(int nt=0;nt<4;nt++)
        mma_bf16(acc2[nt], ap, bv[nt>>1][kt][nt&1], bv[nt>>1][kt][2+(nt&1)]);
    }
    __syncthreads();
    if(c+2<8) issueV(c+2, s);
  }
  // ---- reduce k-quarter partials via sS scratch ----
  #pragma unroll
  for(int nt=0;nt<4;nt++){
    int q0 = wm*16+g, dd = nt*8+2*tg;
    *(float2*)&sS[wk*1024 + q0*32 + dd]     = make_float2(acc2[nt].x, acc2[nt].y);
    *(float2*)&sS[wk*1024 + (q0+8)*32 + dd] = make_float2(acc2[nt].z, acc2[nt].w);
  }
  __syncthreads();
  {
    float4 s4 = make_float4(0.f,0.f,0.f,0.f);
    #pragma unroll
    for(int g2=0; g2<4; g2++){
      float4 v = *(const float4*)&sS[g2*1024 + t*4];
      s4.x+=v.x; s4.y+=v.y; s4.z+=v.z; s4.w+=v.w;
    }
    int oi = t*4;
    int q = oi>>5, dd = oi&31;
    *(float4*)&g_cat[((size_t)(b*4096+n0+q))*256 + h*32 + dd] = s4;
  }
}
#define ATTN1_SMEM 210432

// ---------------- g reduction -------------------------------------------------
__global__ void gred_k(){
  int b = blockIdx.x>>4;
  int ml = threadIdx.x&63;
  int pg = threadIdx.x>>6;
  int m = (blockIdx.x&15)*64 + ml;
  float s = 0.f;
  for(int p=pg; p<512; p+=4)
    s += g_part[((size_t)(b*512+p))*1024 + m];
  __shared__ float red[4][64];
  red[pg][ml] = s;
  __syncthreads();
  if(pg==0)
    g_gsum[b*1024+m] = (red[0][ml]+red[1][ml])+(red[2][ml]+red[3][ml]);
}

// ---------------- branch-2 window attention ----------------------------------
__global__ void attn2_k(){
  __shared__ float sQ[4][16][33], sK[4][16][33], sV[4][16][33];
  __shared__ float sS2[4][16][17];
  int t = threadIdx.x;
  int win = blockIdx.x, b = blockIdx.y;
  int i1 = win>>4, j1 = win&15;
  for(int e=t;e<2048;e+=256){
    int h=e>>9, rem=e&511, tk=rem>>5, dd=rem&31;
    int n = ((i1*4 + (tk>>2))<<6) + j1*4 + (tk&3);
    size_t base = ((size_t)(b*4096+n))*768 + h*32+dd;
    sQ[h][tk][dd] = g_proj1[base+128];
    sK[h][tk][dd] = g_proj1[base+256];
    sV[h][tk][dd] = g_proj1[base+384];
  }
  __syncthreads();
  int h = t>>6, q = (t>>2)&15, kg = t&3;
  #pragma unroll
  for(int k2=0;k2<4;k2++){
    int kk = kg*4+k2;
    float s = 0.f;
    #pragma unroll
    for(int dd=0;dd<32;dd++) s = fmaf(sQ[h][q][dd], sK[h][kk][dd], s);
    sS2[h][q][kk] = s*SCALE1;
  }
  __syncthreads();
  if(kg==0){
    float* row = sS2[h][q];
    float mx=-1e30f;
    #pragma unroll
    for(int kk=0;kk<16;kk++) mx = fmaxf(mx,row[kk]);
    float sm=0.f;
    #pragma unroll
    for(int kk=0;kk<16;kk++){ float p=__expf(row[kk]-mx); row[kk]=p; sm+=p; }
    float inv=1.f/sm;
    #pragma unroll
    for(int kk=0;kk<16;kk++) row[kk]*=inv;
  }
  __syncthreads();
  float acc[8]={};
  int dd0 = kg*8;
  #pragma unroll
  for(int kk=0;kk<16;kk++){
    float p = sS2[h][q][kk];
    #pragma unroll
    for(int u=0;u<8;u++) acc[u] = fmaf(p, sV[h][kk][dd0+u], acc[u]);
  }
  {
    int n = ((i1*4+(q>>2))<<6) + j1*4 + (q&3);
    float* dst = &g_cat[((size_t)(b*4096+n))*256 + 128 + h*32 + dd0];
    #pragma unroll
    for(int u=0;u<8;u++) dst[u] = acc[u];
  }
  if(t<16){
    float s=0.f;
    #pragma unroll
    for(int h2=0;h2<4;h2++)
      #pragma unroll
      for(int q2=0;q2<16;q2++) s += sS2[h2][q2][t];
    int y = i1*4 + (t>>2), x = j1*4 + (t&3);
    g_lm[b*4096 + y*64 + x] = s*(1.f/64.f);
  }
}

// ---------------- depthwise lepe conv + concat add -> hi/lo split ------------
__global__ void lepe_k(const float* __restrict__ lcb){
  int blk = blockIdx.x, c = threadIdx.x;
  int b = blk>>12, pos = blk&4095, y = pos>>6, x = pos&63;
  float acc = lcb[c];
  #pragma unroll
  for(int dy=-1;dy<=1;dy++){
    int yy = y+dy; if((unsigned)yy >= 64u) continue;
    #pragma unroll
    for(int dx=-1;dx<=1;dx++){
      int xx = x+dx; if((unsigned)xx >= 64u) continue;
      int tap = (dy+1)*3 + (dx+1);
      acc = fmaf(g_proj1[((size_t)(b*4096 + yy*64+xx))*768 + 512 + c],
                 g_lwT[tap*256+c], acc);
    }
  }
  float v = g_cat[(size_t)blk*256 + c] + acc;
  bf16 hi, lo; split2(v, hi, lo);
  size_t o = (size_t)blk*768;
  g_prehl[o+c] = hi; g_prehl[o+256+c] = lo; g_prehl[o+512+c] = hi;
}

// ---------------- mask assembly ----------------------------------------------
__global__ void mask_k(float* __restrict__ out){
  int idx = blockIdx.x*256 + threadIdx.x;
  int b = idx>>12, pos = idx&4095, y = pos>>6, x = pos&63;
  float v = g_lm[idx] + g_gsum[b*1024 + (y>>1)*32 + (x>>1)] * (1.f/16384.f);
  out[4194304 + idx] = v;
  out[4210688 + b*4096 + x*64 + y] = v;
}

// ---------------- launch -----------------------------------------------------
extern "C" void kernel_launch(void* const* d_in, const int* in_sizes, int n_in,
                              void* d_out, int out_size)
{
  const float* x    = (const float*)d_in[0];
  const float* q1w  = (const float*)d_in[1];
  const float* q1b  = (const float*)d_in[2];
  const float* kv1w = (const float*)d_in[3];
  const float* kv1b = (const float*)d_in[4];
  const float* q2w  = (const float*)d_in[5];
  const float* q2b  = (const float*)d_in[6];
  const float* kv2w = (const float*)d_in[7];
  const float* kv2b = (const float*)d_in[8];
  const float* lpw  = (const float*)d_in[9];
  const float* lpb  = (const float*)d_in[10];
  const float* lcw  = (const float*)d_in[11];
  const float* lcb  = (const float*)d_in[12];
  const float* srw  = (const float*)d_in[13];
  const float* srb  = (const float*)d_in[14];
  const float* nw   = (const float*)d_in[15];
  const float* nb   = (const float*)d_in[16];
  const float* pw   = (const float*)d_in[17];
  const float* pb   = (const float*)d_in[18];
  float* out = (float*)d_out;

  cudaFuncSetAttribute(attn1_k, cudaFuncAttributeMaxDynamicSharedMemorySize, ATTN1_SMEM);
  cudaFuncSetAttribute(gemm01_k, cudaFuncAttributeMaxDynamicSharedMemorySize, GEMM_SMEM);
  cudaFuncSetAttribute(gemm2_k,  cudaFuncAttributeMaxDynamicSharedMemorySize, GEMM_SMEM);
  cudaFuncSetAttribute(gemm3_k,  cudaFuncAttributeMaxDynamicSharedMemorySize, GEMM_SMEM);

  prep_k<<<256,256>>>(q1w,q2w,kv2w,lpw,q1b,q2b,kv2b,lpb,srw,lcw,kv1w,pw);
  convx_k<<<16384,256>>>(x);
  nop_k<<<1,32>>>();
  gemm01_k<<<832,256,GEMM_SMEM>>>(srb);          // proj1 + q1hl + xs_pre; profiled slot
  attn2_k<<<dim3(256,4),256>>>();
  ln_gelu_k<<<4096,256>>>(nw, nb);
  gemm2_k<<<64,256,GEMM_SMEM>>>(kv1b);           // kv1 -> k1hl / v1T
  attn1_k<<<dim3(128,4,4), 256, ATTN1_SMEM>>>();
  gred_k<<<64,256>>>();
  lepe_k<<<16384,256>>>(lcb);
  gemm3_k<<<256,256,GEMM_SMEM>>>(pb, out);       // proj -> out
  mask_k<<<64,256>>>(out);
}